// round 7
// baseline (speedup 1.0000x reference)
#include <cuda_runtime.h>
#include <cstdint>

// GausSplatingHead: per-point 3D Gaussian covariance from (scale, quaternion).
// R7 = R4 skeleton minus all removable overhead:
//   - scales read directly as 3 scalar __ldcs per point (12B stride is fully
//     sector-efficient) -> no scales smem, no first barrier
//   - rots read as dense float4 __ldcs
//   - output staged in 12KB smem, ONE barrier, one TMA bulk store per tile
//   - wait_group.read (smem-reuse semantics) instead of full completion wait

#define TPB  256
#define TILE 512   // points per block

__device__ __forceinline__ uint32_t smem_u32(const void* p) {
    uint32_t a;
    asm("{ .reg .u64 t; cvta.to.shared.u64 t, %1; cvt.u32.u64 %0, t; }"
        : "=r"(a) : "l"(p));
    return a;
}

__device__ __forceinline__ void cov_from_q(
    float r, float x, float y, float z,
    float s0, float s1, float s2, float* o /*6*/)
{
    float n2 = r * r + x * x + y * y + z * z;
    // R(q/||q||) entries are quadratic in q: fold normalization into the
    // factor 2 -> ss = 2/||q||^2. Algebraically identical to the reference.
    float ss = __fdividef(2.0f, n2);

    float xx = x * x * ss, yy = y * y * ss, zz = z * z * ss;
    float xy = x * y * ss, xz = x * z * ss, yz = y * z * ss;
    float rx = r * x * ss, ry = r * y * ss, rz = r * z * ss;

    float R00 = 1.0f - yy - zz, R01 = xy - rz, R02 = xz + ry;
    float R10 = xy + rz, R11 = 1.0f - xx - zz, R12 = yz - rx;
    float R20 = xz - ry, R21 = yz + rx, R22 = 1.0f - xx - yy;

    float a = s0 * s0, b = s1 * s1, c = s2 * s2;

    o[0] = R00 * R00 * a + R01 * R01 * b + R02 * R02 * c;  // 00
    o[1] = R00 * R10 * a + R01 * R11 * b + R02 * R12 * c;  // 01
    o[2] = R00 * R20 * a + R01 * R21 * b + R02 * R22 * c;  // 02
    o[3] = R10 * R10 * a + R11 * R11 * b + R12 * R12 * c;  // 11
    o[4] = R10 * R20 * a + R11 * R21 * b + R12 * R22 * c;  // 12
    o[5] = R20 * R20 * a + R21 * R21 * b + R22 * R22 * c;  // 22
}

__global__ __launch_bounds__(TPB) void gs_cov_r7_kernel(
    const float* __restrict__ scales,    // [n*3]
    const float4* __restrict__ rots4,    // [n]
    float4* __restrict__ out4,           // [n*6/4]
    int n)
{
    __shared__ __align__(16) float s_out[TILE * 6];      // 12 KB

    const int tid  = threadIdx.x;
    const int base = blockIdx.x * TILE;

    if (base + TILE <= n) {
        // ---- all 8 independent loads issued up front (max MLP) ----
        const int p0 = base + tid;
        const int p1 = base + TPB + tid;

        float4 q0 = __ldcs(&rots4[p0]);
        float4 q1 = __ldcs(&rots4[p1]);
        float s00 = __ldcs(&scales[3 * p0 + 0]);
        float s01 = __ldcs(&scales[3 * p0 + 1]);
        float s02 = __ldcs(&scales[3 * p0 + 2]);
        float s10 = __ldcs(&scales[3 * p1 + 0]);
        float s11 = __ldcs(&scales[3 * p1 + 1]);
        float s12 = __ldcs(&scales[3 * p1 + 2]);

        // ---- compute + stage output (STS.64) ----
        float o0[6], o1[6];
        cov_from_q(q0.x, q0.y, q0.z, q0.w, s00, s01, s02, o0);
        cov_from_q(q1.x, q1.y, q1.z, q1.w, s10, s11, s12, o1);

        float2* so2 = (float2*)s_out;
        so2[3 * tid + 0]         = make_float2(o0[0], o0[1]);
        so2[3 * tid + 1]         = make_float2(o0[2], o0[3]);
        so2[3 * tid + 2]         = make_float2(o0[4], o0[5]);
        so2[3 * (TPB + tid) + 0] = make_float2(o1[0], o1[1]);
        so2[3 * (TPB + tid) + 1] = make_float2(o1[2], o1[3]);
        so2[3 * (TPB + tid) + 2] = make_float2(o1[4], o1[5]);
        __syncthreads();

        // ---- one TMA bulk store per tile ----
        if (tid == 0) {
            asm volatile("fence.proxy.async.shared::cta;" ::: "memory");
            const float* gdst = (const float*)out4 + (size_t)base * 6;
            uint32_t saddr = smem_u32(s_out);
            asm volatile(
                "cp.async.bulk.global.shared::cta.bulk_group [%0], [%1], %2;"
                :: "l"(gdst), "r"(saddr), "n"(TILE * 6 * 4)
                : "memory");
            asm volatile("cp.async.bulk.commit_group;" ::: "memory");
            // only wait until smem can be reused (block exit releases smem)
            asm volatile("cp.async.bulk.wait_group.read 0;" ::: "memory");
        }
    } else {
        // ---- tail tile (rare): scalar global path ----
        const float* rots = (const float*)rots4;
        float* out        = (float*)out4;
#pragma unroll
        for (int p = 0; p < 2; p++) {
            int i = base + p * TPB + tid;
            if (i < n) {
                float o[6];
                cov_from_q(rots[4 * i + 0], rots[4 * i + 1],
                           rots[4 * i + 2], rots[4 * i + 3],
                           scales[3 * i + 0], scales[3 * i + 1],
                           scales[3 * i + 2], o);
#pragma unroll
                for (int k = 0; k < 6; k++) out[6 * i + k] = o[k];
            }
        }
    }
}

extern "C" void kernel_launch(void* const* d_in, const int* in_sizes, int n_in,
                              void* d_out, int out_size)
{
    const float* scales = (const float*)d_in[0];    // [N,3]
    const float4* rots  = (const float4*)d_in[1];   // [N,4]
    float4* out         = (float4*)d_out;           // [N,6]

    int n = in_sizes[0] / 3;
    int blocks = (n + TILE - 1) / TILE;
    gs_cov_r7_kernel<<<blocks, TPB>>>(scales, rots, out, n);
}